// round 14
// baseline (speedup 1.0000x reference)
#include <cuda_runtime.h>
#include <cuda_bf16.h>
#include <cuda_fp16.h>
#include <cstdint>

#define EPSI 1e-7f

// ===========================================================================
// Scratch (__device__ globals; no allocation allowed).
// Qf/Kf/Vf: fp16, [B][nh][W][H][d].   XVf: fp16, [B][nh][H][W][d].
// g_Xh: fp16 x, [pix][c].  g_Wh: fp16 W^T, [p][f][c].
// ===========================================================================
__device__ __half g_Qf[33554432];
__device__ __half g_Kf[33554432];
__device__ __half g_Vf[33554432];
__device__ __half g_XVf[33554432];
__device__ __half g_Xh[33554432];
__device__ __half g_Wh[786432];

// ===========================================================================
// Helpers (sm_80-era tensor path; compiles on plain compute_103 target)
// ===========================================================================
__device__ __forceinline__ uint32_t smem_u32(const void* p) {
    uint32_t a;
    asm("{ .reg .u64 t; cvta.to.shared.u64 t, %1; cvt.u32.u64 %0, t; }"
        : "=r"(a) : "l"(p));
    return a;
}

#define LDMX4(r, addr) \
    asm volatile("ldmatrix.sync.aligned.m8n8.x4.shared.b16 {%0,%1,%2,%3}, [%4];" \
        : "=r"((r)[0]), "=r"((r)[1]), "=r"((r)[2]), "=r"((r)[3]) : "r"(addr))

#define LDMX4T(r, addr) \
    asm volatile("ldmatrix.sync.aligned.m8n8.x4.trans.shared.b16 {%0,%1,%2,%3}, [%4];" \
        : "=r"((r)[0]), "=r"((r)[1]), "=r"((r)[2]), "=r"((r)[3]) : "r"(addr))

// fp16 MMA, fp32 accumulate
__device__ __forceinline__ void mma16816h(float* d, const uint32_t* a, const uint32_t* b) {
    asm volatile(
        "mma.sync.aligned.m16n8k16.row.col.f32.f16.f16.f32 "
        "{%0,%1,%2,%3}, {%4,%5,%6,%7}, {%8,%9}, {%0,%1,%2,%3};"
        : "+f"(d[0]), "+f"(d[1]), "+f"(d[2]), "+f"(d[3])
        : "r"(a[0]), "r"(a[1]), "r"(a[2]), "r"(a[3]), "r"(b[0]), "r"(b[1]));
}

#define CP16(dst, src) \
    asm volatile("cp.async.cg.shared.global [%0], [%1], 16;" \
        :: "r"(dst), "l"((const void*)(src)))

__device__ __forceinline__ uint32_t pack_h2(float f0, float f1) {
    __half2 t = __floats2half2_rn(f0, f1);   // x = f0 (low half)
    return *reinterpret_cast<uint32_t*>(&t);
}

// SW128 swizzle on byte offsets (rows are 128 B)
#define ASW(off) ((uint32_t)(off) ^ ((((uint32_t)(off)) >> 3) & 0x70u))

// ===========================================================================
// x -> fp16 (one float4 per thread)
// ===========================================================================
__global__ void __launch_bounds__(256) xsplit_kernel(const float* __restrict__ x)
{
    const int i = blockIdx.x * 256 + threadIdx.x;
    float4 v = ((const float4*)x)[i];
    ((__half2*)g_Xh)[i * 2 + 0] = __floats2half2_rn(v.x, v.y);
    ((__half2*)g_Xh)[i * 2 + 1] = __floats2half2_rn(v.z, v.w);
}

// ===========================================================================
// W -> transposed fp16: WT[p][f][c] = W_p[c][f]
// ===========================================================================
__global__ void __launch_bounds__(256) wsplit_kernel(
    const float* __restrict__ wq, const float* __restrict__ wk,
    const float* __restrict__ wv)
{
    const int idx = blockIdx.x * 256 + threadIdx.x;
    const int p = idx >> 18;
    const int f = (idx >> 9) & 511;
    const int c = idx & 511;
    const float* __restrict__ W = (p == 0) ? wq : (p == 1) ? wk : wv;
    g_Wh[idx] = __float2half(W[c * 512 + f]);
}

// ===========================================================================
// Projection: fp16 mma.sync, CTA tile 128m x 256n, 512 threads (4m x 4n
// warps, warp tile 32x64, acc=64 regs), 1 CTA/SM, BK=32 depth-2 cp.async.
// A-tile amortized over 2 n-tiles -> copy bytes per output unit drop 25%.
// smem stage = A(128x80) + B(256x80) = 30720 B; 2 stages = 61440 B.
// Grid 1-D: (which, n-half) fastest, m-tile slowest for L2 A-reuse.
// ===========================================================================
#define TPITCH 80
#define A_TILE 10240
#define STAGE_B 30720
#define PROJ_SMEM 61440

__global__ void __launch_bounds__(512, 1) proj_mma_kernel(
    const float* __restrict__ bq, const float* __restrict__ bk,
    const float* __restrict__ bv)
{
    extern __shared__ char smc[];
    const uint32_t sb = smem_u32(smc);

    const int tid  = threadIdx.x;
    const int lane = tid & 31;
    const int wid  = tid >> 5;         // 0..15
    const int wm   = wid & 3;          // m-strip (32 rows)
    const int wn   = wid >> 2;         // n-strip (64 cols of 256)

    const int bx    = blockIdx.x;
    const int which = bx % 3;
    const int n0    = ((bx / 3) & 1) * 256;
    const int m0    = (bx / 6) * 128;

    const __half* __restrict__ Wp = g_Wh + which * 262144;
    const float* __restrict__ bias = (which == 0) ? bq : (which == 1) ? bk : bv;
    __half* __restrict__ outp = (which == 0) ? g_Qf : (which == 1) ? g_Kf : g_Vf;

    float acc[2][8][4];
#pragma unroll
    for (int a = 0; a < 2; a++)
#pragma unroll
        for (int b = 0; b < 8; b++)
#pragma unroll
            for (int c = 0; c < 4; c++) acc[a][b][c] = 0.0f;

    auto issue = [&](int c) {
        const int k0 = c * 32;
        const uint32_t st = sb + (c & 1) * STAGE_B;
        // A: 512 slots, one per thread: row = tid>>2 (0..127), ch = tid&3
        {
            const int row = tid >> 2;
            const int ch  = tid & 3;
            CP16(st + row * TPITCH + ch * 16,
                 g_Xh + (m0 + row) * 512 + k0 + ch * 8);
        }
        // B: 1024 slots, two per thread: row 0..255
#pragma unroll
        for (int i = 0; i < 2; i++) {
            const int slot = tid + i * 512;
            const int row  = slot >> 2;
            const int ch   = slot & 3;
            CP16(st + A_TILE + row * TPITCH + ch * 16,
                 Wp + (n0 + row) * 512 + k0 + ch * 8);
        }
        asm volatile("cp.async.commit_group;");
    };

    issue(0);
    for (int c = 0; c < 16; c++) {
        if (c < 15) {
            issue(c + 1);
            asm volatile("cp.async.wait_group 1;");
        } else {
            asm volatile("cp.async.wait_group 0;");
        }
        __syncthreads();

        const uint32_t st = sb + (c & 1) * STAGE_B;
#pragma unroll
        for (int ks = 0; ks < 2; ks++) {
            uint32_t af[2][4];
            const int al = lane & 15;
            const int ac = ks * 2 + (lane >> 4);
#pragma unroll
            for (int mt = 0; mt < 2; mt++) {
                const uint32_t ad = st + (wm * 32 + mt * 16 + al) * TPITCH + ac * 16;
                LDMX4(af[mt], ad);
            }
            const int br = (lane >> 4) * 8 + (lane & 7);
            const int bc = ks * 2 + ((lane >> 3) & 1);
#pragma unroll
            for (int p = 0; p < 4; p++) {
                const uint32_t bd = st + A_TILE
                                  + (wn * 64 + p * 16 + br) * TPITCH + bc * 16;
                uint32_t bh[4];
                LDMX4(bh, bd);
#pragma unroll
                for (int mt = 0; mt < 2; mt++) {
                    mma16816h(acc[mt][2 * p],     af[mt], &bh[0]);
                    mma16816h(acc[mt][2 * p + 1], af[mt], &bh[2]);
                }
            }
        }
        __syncthreads();
    }

    // ---- epilogue: bias, convert fp16, scatter into [B][nh][W][H][d] ----
    const int g  = lane >> 2;
    const int tg = lane & 3;
#pragma unroll
    for (int mt = 0; mt < 2; mt++) {
#pragma unroll
        for (int half = 0; half < 2; half++) {
            const int pix = m0 + wm * 32 + mt * 16 + g + half * 8;
            const int b = pix >> 14;
            const int h = (pix >> 7) & 127;
            const int w = pix & 127;
#pragma unroll
            for (int nt = 0; nt < 8; nt++) {
                const int f  = n0 + wn * 64 + nt * 8 + tg * 2;
                const int nh = f >> 6;
                const int dd = f & 63;
                float2 bb = *(const float2*)(bias + f);
                const float ox = acc[mt][nt][half * 2 + 0] + bb.x;
                const float oy = acc[mt][nt][half * 2 + 1] + bb.y;
                const int off = (((b * 8 + nh) * 128 + w) * 128 + h) * 64 + dd;
                *(__half2*)(outp + off) = __floats2half2_rn(ox, oy);
            }
        }
    }
}

// ===========================================================================
// Tensor-core axial attention — fp16 single-product (unchanged from R13).
// smem 48 KB: Q 0, K 16K, V 32K; 128 rows x 128 B, SW128-swizzled.
// ===========================================================================
#define AQ 0
#define AK 16384
#define AV 32768
#define ATTN_SMEM 49152

__global__ void __launch_bounds__(256, 2) attn_mma_kernel(float* __restrict__ out, const int stage)
{
    extern __shared__ char sm[];
    const uint32_t sb = smem_u32(sm);

    const int tid  = threadIdx.x;
    const int lane = tid & 31;
    const int wid  = tid >> 5;
    const int x_   = blockIdx.x;
    const int b8n  = blockIdx.z * 8 + blockIdx.y;

    const __half* __restrict__ Vp = (stage == 1) ? g_Vf : g_XVf;

    int qbase, rstride;
    if (stage == 1) {
        qbase   = (b8n * 128 + x_) * 8192;
        rstride = 64;
    } else {
        qbase   = b8n * 1048576 + x_ * 64;
        rstride = 8192;
    }
    const int vbase = (b8n * 128 + x_) * 8192;

    // ---- group 0: Q,K tiles ----
    for (int idx = tid; idx < 1024; idx += 256) {
        const int row = idx >> 3;
        const int ch  = idx & 7;
        const int qoff = qbase + row * rstride + ch * 8;
        const uint32_t dst = ASW(row * 128 + ch * 16);
        CP16(sb + AQ + dst, g_Qf + qoff);
        CP16(sb + AK + dst, g_Kf + qoff);
    }
    asm volatile("cp.async.commit_group;");
    // ---- group 1: V tile ----
    for (int idx = tid; idx < 1024; idx += 256) {
        const int row = idx >> 3;
        const int ch  = idx & 7;
        const uint32_t dst = ASW(row * 128 + ch * 16);
        CP16(sb + AV + dst, Vp + vbase + row * 64 + ch * 8);
    }
    asm volatile("cp.async.commit_group;");

    asm volatile("cp.async.wait_group 1;");   // Q,K ready; V may still fly
    __syncthreads();

    // ---- S = Q * K^T  (warp strip m16 x N=128) ----
    float sacc[16][4];
#pragma unroll
    for (int j = 0; j < 16; j++)
#pragma unroll
        for (int c = 0; c < 4; c++) sacc[j][c] = 0.0f;

    const int m0w = wid * 16;
    const int alr = lane & 15;
    const int alc = lane >> 4;
    const int blr = ((lane >> 4) << 3) + (lane & 7);
    const int blc = (lane >> 3) & 1;

#pragma unroll
    for (int kt = 0; kt < 4; kt++) {
        uint32_t af[4];
        const uint32_t aa = sb + AQ + ASW((m0w + alr) * 128 + (kt * 2 + alc) * 16);
        LDMX4(af, aa);
#pragma unroll
        for (int p = 0; p < 8; p++) {
            const uint32_t ba = sb + AK + ASW((p * 16 + blr) * 128 + (kt * 2 + blc) * 16);
            uint32_t bh[4];
            LDMX4(bh, ba);
            mma16816h(sacc[2 * p],     af, &bh[0]);
            mma16816h(sacc[2 * p + 1], af, &bh[2]);
        }
    }

    // ---- clip(+-(1-eps)), /8, softmax per row, clip [eps,1-eps] ----
    {
        const float lo = -1.0f + EPSI, hi = 1.0f - EPSI;
#pragma unroll
        for (int j = 0; j < 16; j++)
#pragma unroll
            for (int c = 0; c < 4; c++)
                sacc[j][c] = fminf(fmaxf(sacc[j][c], lo), hi) * 0.125f;

        float mx0 = -1e30f, mx1 = -1e30f;
#pragma unroll
        for (int j = 0; j < 16; j++) {
            mx0 = fmaxf(mx0, fmaxf(sacc[j][0], sacc[j][1]));
            mx1 = fmaxf(mx1, fmaxf(sacc[j][2], sacc[j][3]));
        }
        mx0 = fmaxf(mx0, __shfl_xor_sync(0xffffffffu, mx0, 1));
        mx0 = fmaxf(mx0, __shfl_xor_sync(0xffffffffu, mx0, 2));
        mx1 = fmaxf(mx1, __shfl_xor_sync(0xffffffffu, mx1, 1));
        mx1 = fmaxf(mx1, __shfl_xor_sync(0xffffffffu, mx1, 2));

        float s0 = 0.0f, s1 = 0.0f;
#pragma unroll
        for (int j = 0; j < 16; j++) {
            sacc[j][0] = __expf(sacc[j][0] - mx0);
            sacc[j][1] = __expf(sacc[j][1] - mx0);
            sacc[j][2] = __expf(sacc[j][2] - mx1);
            sacc[j][3] = __expf(sacc[j][3] - mx1);
            s0 += sacc[j][0] + sacc[j][1];
            s1 += sacc[j][2] + sacc[j][3];
        }
        s0 += __shfl_xor_sync(0xffffffffu, s0, 1);
        s0 += __shfl_xor_sync(0xffffffffu, s0, 2);
        s1 += __shfl_xor_sync(0xffffffffu, s1, 1);
        s1 += __shfl_xor_sync(0xffffffffu, s1, 2);
        const float i0 = 1.0f / s0, i1 = 1.0f / s1;
        const float alo2 = EPSI, ahi2 = 1.0f - EPSI;
#pragma unroll
        for (int j = 0; j < 16; j++) {
            sacc[j][0] = fminf(fmaxf(sacc[j][0] * i0, alo2), ahi2);
            sacc[j][1] = fminf(fmaxf(sacc[j][1] * i0, alo2), ahi2);
            sacc[j][2] = fminf(fmaxf(sacc[j][2] * i1, alo2), ahi2);
            sacc[j][3] = fminf(fmaxf(sacc[j][3] * i1, alo2), ahi2);
        }
    }

    asm volatile("cp.async.wait_group 0;");   // V ready
    __syncthreads();

    // ---- O = P * V  (m16 x N=64, K=128); V via ldmatrix.trans ----
    float oacc[8][4];
#pragma unroll
    for (int j = 0; j < 8; j++)
#pragma unroll
        for (int c = 0; c < 4; c++) oacc[j][c] = 0.0f;

    const int vr = (lane & 7) + ((lane >> 3) & 1) * 8;
    const int vc = lane >> 4;

#pragma unroll
    for (int jj = 0; jj < 8; jj++) {
        const int e = 2 * jj, o = 2 * jj + 1;
        uint32_t pf[4];
        pf[0] = pack_h2(sacc[e][0], sacc[e][1]);
        pf[1] = pack_h2(sacc[e][2], sacc[e][3]);
        pf[2] = pack_h2(sacc[o][0], sacc[o][1]);
        pf[3] = pack_h2(sacc[o][2], sacc[o][3]);
#pragma unroll
        for (int np = 0; np < 4; np++) {
            const uint32_t ba = sb + AV
                + ASW((jj * 16 + vr) * 128 + np * 32 + vc * 16);
            uint32_t bh[4];
            LDMX4T(bh, ba);
            mma16816h(oacc[2 * np],     pf, &bh[0]);
            mma16816h(oacc[2 * np + 1], pf, &bh[2]);
        }
    }

    // ---- epilogue ----
    const int g  = lane >> 2;
    const int t4 = lane & 3;
    if (stage == 1) {
        // XV fp16 [b][n][h][w][d]: row = h, col = d, w = x_
        const int base = b8n * 1048576 + x_ * 64;
#pragma unroll
        for (int nt = 0; nt < 8; nt++) {
            const int d = nt * 8 + t4 * 2;
            const int off0 = base + (m0w + g) * 8192 + d;
            const int off1 = base + (m0w + g + 8) * 8192 + d;
            *(__half2*)(g_XVf + off0) = __floats2half2_rn(oacc[nt][0], oacc[nt][1]);
            *(__half2*)(g_XVf + off1) = __floats2half2_rn(oacc[nt][2], oacc[nt][3]);
        }
    } else {
        // out[b][h=x_][w=row][c=d*8+n]
        const int n = b8n & 7;
        const int b = b8n >> 3;
        const int base = (b * 128 + x_) * 65536 + n;
#pragma unroll
        for (int nt = 0; nt < 8; nt++) {
            const int d = nt * 8 + t4 * 2;
            out[base + (m0w + g) * 512 + d * 8]           = oacc[nt][0];
            out[base + (m0w + g) * 512 + (d + 1) * 8]     = oacc[nt][1];
            out[base + (m0w + g + 8) * 512 + d * 8]       = oacc[nt][2];
            out[base + (m0w + g + 8) * 512 + (d + 1) * 8] = oacc[nt][3];
        }
    }
}

// ---------------------------------------------------------------------------
extern "C" void kernel_launch(void* const* d_in, const int* in_sizes, int n_in,
                              void* d_out, int out_size)
{
    const float* x  = (const float*)d_in[0];
    const float* wq = (const float*)d_in[1];
    const float* bq = (const float*)d_in[2];
    const float* wk = (const float*)d_in[3];
    const float* bk = (const float*)d_in[4];
    const float* wv = (const float*)d_in[5];
    const float* bv = (const float*)d_in[6];
    float* out = (float*)d_out;

    cudaFuncSetAttribute((const void*)attn_mma_kernel,
                         cudaFuncAttributeMaxDynamicSharedMemorySize, ATTN_SMEM);
    cudaFuncSetAttribute((const void*)proj_mma_kernel,
                         cudaFuncAttributeMaxDynamicSharedMemorySize, PROJ_SMEM);

    xsplit_kernel<<<32768, 256>>>(x);
    wsplit_kernel<<<3072, 256>>>(wq, wk, wv);

    // 3072 CTAs: which fastest, then n-half, then m-tile (L2 A-reuse)
    proj_mma_kernel<<<3072, 512, PROJ_SMEM>>>(bq, bk, bv);

    dim3 ag(128, 8, 4);
    attn_mma_kernel<<<ag, 256, ATTN_SMEM>>>(out, 1);
    attn_mma_kernel<<<ag, 256, ATTN_SMEM>>>(out, 2);
}

// round 16
// speedup vs baseline: 1.1080x; 1.1080x over previous
#include <cuda_runtime.h>
#include <cuda_bf16.h>
#include <cuda_fp16.h>
#include <cstdint>

#define EPSI 1e-7f

// ===========================================================================
// Scratch (__device__ globals; no allocation allowed).
// Qf/Kf/Vf: fp16, [B][nh][W][H][d].   XVf: fp16, [B][nh][H][W][d].
// g_Xh: fp16 x, [pix][c].  g_Wh: fp16 W^T, [p][f][c].
// ===========================================================================
__device__ __half g_Qf[33554432];
__device__ __half g_Kf[33554432];
__device__ __half g_Vf[33554432];
__device__ __half g_XVf[33554432];
__device__ __half g_Xh[33554432];
__device__ __half g_Wh[786432];

// ===========================================================================
// Helpers (sm_80-era tensor path; compiles on plain compute_103 target)
// ===========================================================================
__device__ __forceinline__ uint32_t smem_u32(const void* p) {
    uint32_t a;
    asm("{ .reg .u64 t; cvta.to.shared.u64 t, %1; cvt.u32.u64 %0, t; }"
        : "=r"(a) : "l"(p));
    return a;
}

#define LDMX4(r, addr) \
    asm volatile("ldmatrix.sync.aligned.m8n8.x4.shared.b16 {%0,%1,%2,%3}, [%4];" \
        : "=r"((r)[0]), "=r"((r)[1]), "=r"((r)[2]), "=r"((r)[3]) : "r"(addr))

#define LDMX4T(r, addr) \
    asm volatile("ldmatrix.sync.aligned.m8n8.x4.trans.shared.b16 {%0,%1,%2,%3}, [%4];" \
        : "=r"((r)[0]), "=r"((r)[1]), "=r"((r)[2]), "=r"((r)[3]) : "r"(addr))

// fp16 MMA, fp32 accumulate
__device__ __forceinline__ void mma16816h(float* d, const uint32_t* a, const uint32_t* b) {
    asm volatile(
        "mma.sync.aligned.m16n8k16.row.col.f32.f16.f16.f32 "
        "{%0,%1,%2,%3}, {%4,%5,%6,%7}, {%8,%9}, {%0,%1,%2,%3};"
        : "+f"(d[0]), "+f"(d[1]), "+f"(d[2]), "+f"(d[3])
        : "r"(a[0]), "r"(a[1]), "r"(a[2]), "r"(a[3]), "r"(b[0]), "r"(b[1]));
}

#define CP16(dst, src) \
    asm volatile("cp.async.cg.shared.global [%0], [%1], 16;" \
        :: "r"(dst), "l"((const void*)(src)))

__device__ __forceinline__ uint32_t pack_h2(float f0, float f1) {
    __half2 t = __floats2half2_rn(f0, f1);   // x = f0 (low half)
    return *reinterpret_cast<uint32_t*>(&t);
}

// SW128 swizzle on byte offsets (rows are 128 B)
#define ASW(off) ((uint32_t)(off) ^ ((((uint32_t)(off)) >> 3) & 0x70u))

// ===========================================================================
// x -> fp16 and W -> transposed fp16 in one launch.
// blocks 0..32767: x (one float4 per thread).  blocks 32768+: W transpose.
// ===========================================================================
__global__ void __launch_bounds__(256) split_kernel(
    const float* __restrict__ x,
    const float* __restrict__ wq, const float* __restrict__ wk,
    const float* __restrict__ wv)
{
    if (blockIdx.x < 32768) {
        const int i = blockIdx.x * 256 + threadIdx.x;
        float4 v = ((const float4*)x)[i];
        ((__half2*)g_Xh)[i * 2 + 0] = __floats2half2_rn(v.x, v.y);
        ((__half2*)g_Xh)[i * 2 + 1] = __floats2half2_rn(v.z, v.w);
    } else {
        const int idx = (blockIdx.x - 32768) * 256 + threadIdx.x;
        const int p = idx >> 18;
        const int f = (idx >> 9) & 511;
        const int c = idx & 511;
        const float* __restrict__ W = (p == 0) ? wq : (p == 1) ? wk : wv;
        g_Wh[idx] = __float2half(W[c * 512 + f]);
    }
}

// ===========================================================================
// Projection: fp16 mma.sync, CTA 128x128, 256 threads (4m x 2n warps),
// 2 CTAs/SM, BK=32, 3-stage cp.async pipeline with ONE barrier per chunk
// (issue-after-barrier: barrier at iter c proves compute(c-1) done, so
// filling buffer (c+2)%3 == (c-1)%3 afterwards is race-free).
// smem: 3 stages x [A|B] x 128 rows x 80 B = 61440 B.
// Grid 1-D: (which, n-tile) fastest for L2 A-reuse.
// ===========================================================================
#define TPITCH 80
#define TILE_B 10240
#define STAGE_B 20480
#define PROJ_SMEM 61440

__global__ void __launch_bounds__(256, 2) proj_mma_kernel(
    const float* __restrict__ bq, const float* __restrict__ bk,
    const float* __restrict__ bv)
{
    extern __shared__ char smc[];
    const uint32_t sb = smem_u32(smc);

    const int tid  = threadIdx.x;
    const int lane = tid & 31;
    const int wid  = tid >> 5;
    const int wm   = wid & 3;
    const int wn   = wid >> 2;

    const int bx    = blockIdx.x;
    const int which = bx % 3;
    const int n0    = ((bx / 3) & 3) * 128;
    const int m0    = (bx / 12) * 128;

    const __half* __restrict__ Wp = g_Wh + which * 262144;
    const float* __restrict__ bias = (which == 0) ? bq : (which == 1) ? bk : bv;
    __half* __restrict__ outp = (which == 0) ? g_Qf : (which == 1) ? g_Kf : g_Vf;

    float acc[2][8][4];
#pragma unroll
    for (int a = 0; a < 2; a++)
#pragma unroll
        for (int b = 0; b < 8; b++)
#pragma unroll
            for (int c = 0; c < 4; c++) acc[a][b][c] = 0.0f;

    auto issue = [&](int c) {
        const int k0 = c * 32;
        const uint32_t st = sb + (c % 3) * STAGE_B;
#pragma unroll
        for (int i = 0; i < 2; i++) {
            const int slot = tid + i * 256;        // 0..511
            const int row  = slot >> 2;            // 0..127
            const int ch   = slot & 3;             // 16B chunk (8 fp16)
            const uint32_t off = row * TPITCH + ch * 16;
            CP16(st + off,          g_Xh + (m0 + row) * 512 + k0 + ch * 8);
            CP16(st + TILE_B + off, Wp   + (n0 + row) * 512 + k0 + ch * 8);
        }
        asm volatile("cp.async.commit_group;");
    };

    issue(0);
    issue(1);
    for (int c = 0; c < 16; c++) {
        asm volatile("cp.async.wait_group 1;");   // chunk c landed
        __syncthreads();                          // publish c; (c-1)%3 free
        if (c < 14) issue(c + 2);                 // after barrier: race-free

        const uint32_t st = sb + (c % 3) * STAGE_B;
#pragma unroll
        for (int ks = 0; ks < 2; ks++) {
            uint32_t af[2][4];
            const int al = lane & 15;
            const int ac = ks * 2 + (lane >> 4);
#pragma unroll
            for (int mt = 0; mt < 2; mt++) {
                const uint32_t ad = st + (wm * 32 + mt * 16 + al) * TPITCH + ac * 16;
                LDMX4(af[mt], ad);
            }
            const int br = (lane >> 4) * 8 + (lane & 7);
            const int bc = ks * 2 + ((lane >> 3) & 1);
#pragma unroll
            for (int p = 0; p < 4; p++) {
                const uint32_t bd = st + TILE_B
                                  + (wn * 64 + p * 16 + br) * TPITCH + bc * 16;
                uint32_t bh[4];
                LDMX4(bh, bd);
#pragma unroll
                for (int mt = 0; mt < 2; mt++) {
                    mma16816h(acc[mt][2 * p],     af[mt], &bh[0]);
                    mma16816h(acc[mt][2 * p + 1], af[mt], &bh[2]);
                }
            }
        }
    }

    // ---- epilogue: bias, convert fp16, scatter into [B][nh][W][H][d] ----
    const int g  = lane >> 2;
    const int tg = lane & 3;
#pragma unroll
    for (int mt = 0; mt < 2; mt++) {
#pragma unroll
        for (int half = 0; half < 2; half++) {
            const int pix = m0 + wm * 32 + mt * 16 + g + half * 8;
            const int b = pix >> 14;
            const int h = (pix >> 7) & 127;
            const int w = pix & 127;
#pragma unroll
            for (int nt = 0; nt < 8; nt++) {
                const int f  = n0 + wn * 64 + nt * 8 + tg * 2;
                const int nh = f >> 6;
                const int dd = f & 63;
                float2 bb = *(const float2*)(bias + f);
                const float ox = acc[mt][nt][half * 2 + 0] + bb.x;
                const float oy = acc[mt][nt][half * 2 + 1] + bb.y;
                const int off = (((b * 8 + nh) * 128 + w) * 128 + h) * 64 + dd;
                *(__half2*)(outp + off) = __floats2half2_rn(ox, oy);
            }
        }
    }
}

// ===========================================================================
// Tensor-core axial attention — fp16 single-product (unchanged from R13).
// smem 48 KB: Q 0, K 16K, V 32K; 128 rows x 128 B, SW128-swizzled.
// ===========================================================================
#define AQ 0
#define AK 16384
#define AV 32768
#define ATTN_SMEM 49152

__global__ void __launch_bounds__(256, 2) attn_mma_kernel(float* __restrict__ out, const int stage)
{
    extern __shared__ char sm[];
    const uint32_t sb = smem_u32(sm);

    const int tid  = threadIdx.x;
    const int lane = tid & 31;
    const int wid  = tid >> 5;
    const int x_   = blockIdx.x;
    const int b8n  = blockIdx.z * 8 + blockIdx.y;

    const __half* __restrict__ Vp = (stage == 1) ? g_Vf : g_XVf;

    int qbase, rstride;
    if (stage == 1) {
        qbase   = (b8n * 128 + x_) * 8192;
        rstride = 64;
    } else {
        qbase   = b8n * 1048576 + x_ * 64;
        rstride = 8192;
    }
    const int vbase = (b8n * 128 + x_) * 8192;

    // ---- group 0: Q,K tiles ----
    for (int idx = tid; idx < 1024; idx += 256) {
        const int row = idx >> 3;
        const int ch  = idx & 7;
        const int qoff = qbase + row * rstride + ch * 8;
        const uint32_t dst = ASW(row * 128 + ch * 16);
        CP16(sb + AQ + dst, g_Qf + qoff);
        CP16(sb + AK + dst, g_Kf + qoff);
    }
    asm volatile("cp.async.commit_group;");
    // ---- group 1: V tile ----
    for (int idx = tid; idx < 1024; idx += 256) {
        const int row = idx >> 3;
        const int ch  = idx & 7;
        const uint32_t dst = ASW(row * 128 + ch * 16);
        CP16(sb + AV + dst, Vp + vbase + row * 64 + ch * 8);
    }
    asm volatile("cp.async.commit_group;");

    asm volatile("cp.async.wait_group 1;");   // Q,K ready; V may still fly
    __syncthreads();

    // ---- S = Q * K^T  (warp strip m16 x N=128) ----
    float sacc[16][4];
#pragma unroll
    for (int j = 0; j < 16; j++)
#pragma unroll
        for (int c = 0; c < 4; c++) sacc[j][c] = 0.0f;

    const int m0w = wid * 16;
    const int alr = lane & 15;
    const int alc = lane >> 4;
    const int blr = ((lane >> 4) << 3) + (lane & 7);
    const int blc = (lane >> 3) & 1;

#pragma unroll
    for (int kt = 0; kt < 4; kt++) {
        uint32_t af[4];
        const uint32_t aa = sb + AQ + ASW((m0w + alr) * 128 + (kt * 2 + alc) * 16);
        LDMX4(af, aa);
#pragma unroll
        for (int p = 0; p < 8; p++) {
            const uint32_t ba = sb + AK + ASW((p * 16 + blr) * 128 + (kt * 2 + blc) * 16);
            uint32_t bh[4];
            LDMX4(bh, ba);
            mma16816h(sacc[2 * p],     af, &bh[0]);
            mma16816h(sacc[2 * p + 1], af, &bh[2]);
        }
    }

    // ---- clip(+-(1-eps)), /8, softmax per row, clip [eps,1-eps] ----
    {
        const float lo = -1.0f + EPSI, hi = 1.0f - EPSI;
#pragma unroll
        for (int j = 0; j < 16; j++)
#pragma unroll
            for (int c = 0; c < 4; c++)
                sacc[j][c] = fminf(fmaxf(sacc[j][c], lo), hi) * 0.125f;

        float mx0 = -1e30f, mx1 = -1e30f;
#pragma unroll
        for (int j = 0; j < 16; j++) {
            mx0 = fmaxf(mx0, fmaxf(sacc[j][0], sacc[j][1]));
            mx1 = fmaxf(mx1, fmaxf(sacc[j][2], sacc[j][3]));
        }
        mx0 = fmaxf(mx0, __shfl_xor_sync(0xffffffffu, mx0, 1));
        mx0 = fmaxf(mx0, __shfl_xor_sync(0xffffffffu, mx0, 2));
        mx1 = fmaxf(mx1, __shfl_xor_sync(0xffffffffu, mx1, 1));
        mx1 = fmaxf(mx1, __shfl_xor_sync(0xffffffffu, mx1, 2));

        float s0 = 0.0f, s1 = 0.0f;
#pragma unroll
        for (int j = 0; j < 16; j++) {
            sacc[j][0] = __expf(sacc[j][0] - mx0);
            sacc[j][1] = __expf(sacc[j][1] - mx0);
            sacc[j][2] = __expf(sacc[j][2] - mx1);
            sacc[j][3] = __expf(sacc[j][3] - mx1);
            s0 += sacc[j][0] + sacc[j][1];
            s1 += sacc[j][2] + sacc[j][3];
        }
        s0 += __shfl_xor_sync(0xffffffffu, s0, 1);
        s0 += __shfl_xor_sync(0xffffffffu, s0, 2);
        s1 += __shfl_xor_sync(0xffffffffu, s1, 1);
        s1 += __shfl_xor_sync(0xffffffffu, s1, 2);
        const float i0 = 1.0f / s0, i1 = 1.0f / s1;
        const float alo2 = EPSI, ahi2 = 1.0f - EPSI;
#pragma unroll
        for (int j = 0; j < 16; j++) {
            sacc[j][0] = fminf(fmaxf(sacc[j][0] * i0, alo2), ahi2);
            sacc[j][1] = fminf(fmaxf(sacc[j][1] * i0, alo2), ahi2);
            sacc[j][2] = fminf(fmaxf(sacc[j][2] * i1, alo2), ahi2);
            sacc[j][3] = fminf(fmaxf(sacc[j][3] * i1, alo2), ahi2);
        }
    }

    asm volatile("cp.async.wait_group 0;");   // V ready
    __syncthreads();

    // ---- O = P * V  (m16 x N=64, K=128); V via ldmatrix.trans ----
    float oacc[8][4];
#pragma unroll
    for (int j = 0; j < 8; j++)
#pragma unroll
        for (int c = 0; c < 4; c++) oacc[j][c] = 0.0f;

    const int vr = (lane & 7) + ((lane >> 3) & 1) * 8;
    const int vc = lane >> 4;

#pragma unroll
    for (int jj = 0; jj < 8; jj++) {
        const int e = 2 * jj, o = 2 * jj + 1;
        uint32_t pf[4];
        pf[0] = pack_h2(sacc[e][0], sacc[e][1]);
        pf[1] = pack_h2(sacc[e][2], sacc[e][3]);
        pf[2] = pack_h2(sacc[o][0], sacc[o][1]);
        pf[3] = pack_h2(sacc[o][2], sacc[o][3]);
#pragma unroll
        for (int np = 0; np < 4; np++) {
            const uint32_t ba = sb + AV
                + ASW((jj * 16 + vr) * 128 + np * 32 + vc * 16);
            uint32_t bh[4];
            LDMX4T(bh, ba);
            mma16816h(oacc[2 * np],     pf, &bh[0]);
            mma16816h(oacc[2 * np + 1], pf, &bh[2]);
        }
    }

    // ---- epilogue ----
    const int g  = lane >> 2;
    const int t4 = lane & 3;
    if (stage == 1) {
        // XV fp16 [b][n][h][w][d]: row = h, col = d, w = x_
        const int base = b8n * 1048576 + x_ * 64;
#pragma unroll
        for (int nt = 0; nt < 8; nt++) {
            const int d = nt * 8 + t4 * 2;
            const int off0 = base + (m0w + g) * 8192 + d;
            const int off1 = base + (m0w + g + 8) * 8192 + d;
            *(__half2*)(g_XVf + off0) = __floats2half2_rn(oacc[nt][0], oacc[nt][1]);
            *(__half2*)(g_XVf + off1) = __floats2half2_rn(oacc[nt][2], oacc[nt][3]);
        }
    } else {
        // out[b][h=x_][w=row][c=d*8+n]
        const int n = b8n & 7;
        const int b = b8n >> 3;
        const int base = (b * 128 + x_) * 65536 + n;
#pragma unroll
        for (int nt = 0; nt < 8; nt++) {
            const int d = nt * 8 + t4 * 2;
            out[base + (m0w + g) * 512 + d * 8]           = oacc[nt][0];
            out[base + (m0w + g) * 512 + (d + 1) * 8]     = oacc[nt][1];
            out[base + (m0w + g + 8) * 512 + d * 8]       = oacc[nt][2];
            out[base + (m0w + g + 8) * 512 + (d + 1) * 8] = oacc[nt][3];
        }
    }
}

// ---------------------------------------------------------------------------
extern "C" void kernel_launch(void* const* d_in, const int* in_sizes, int n_in,
                              void* d_out, int out_size)
{
    const float* x  = (const float*)d_in[0];
    const float* wq = (const float*)d_in[1];
    const float* bq = (const float*)d_in[2];
    const float* wk = (const float*)d_in[3];
    const float* bk = (const float*)d_in[4];
    const float* wv = (const float*)d_in[5];
    const float* bv = (const float*)d_in[6];
    float* out = (float*)d_out;

    cudaFuncSetAttribute((const void*)attn_mma_kernel,
                         cudaFuncAttributeMaxDynamicSharedMemorySize, ATTN_SMEM);
    cudaFuncSetAttribute((const void*)proj_mma_kernel,
                         cudaFuncAttributeMaxDynamicSharedMemorySize, PROJ_SMEM);

    split_kernel<<<35840, 256>>>(x, wq, wk, wv);

    // 6144 CTAs: which fastest, then n-tile, then m-tile (L2 A-reuse)
    proj_mma_kernel<<<6144, 256, PROJ_SMEM>>>(bq, bk, bv);

    dim3 ag(128, 8, 4);
    attn_mma_kernel<<<ag, 256, ATTN_SMEM>>>(out, 1);
    attn_mma_kernel<<<ag, 256, ATTN_SMEM>>>(out, 2);
}